// round 16
// baseline (speedup 1.0000x reference)
#include <cuda_runtime.h>
#include <cuda_fp16.h>
#include <cstdint>
#include <math.h>

#define B_   2
#define C_   128
#define H_   128
#define W_   128
#define HR   64
#define L_   4096
#define EPS_ 0.0001f
#define SCALE_ 10.0f
#define NPC  32
#define CAP  32
#define THRESH 5.9604645e-8f
#define F_FULL 1152.0f

// ---------------- scratch ----------------------------------------------------
__device__ __half g_xd [(size_t)B_ * L_ * 128];  // [b][q][c]
__device__ float  g_S2 [B_ * L_];
__device__ __half g_R  [(size_t)B_ * L_ * L_];   // [b][p][q] correlation
__device__ __half g_att[(size_t)B_ * L_ * L_];   // [b][r][c] logits (sparsely stored)
__device__ float  g_rscale[B_ * L_];
__device__ float  g_mfilt[B_ * L_];
__device__ float  g_diag[B_ * L_];                // diagonal logit lower bound for M
__device__ float  g_statm[(size_t)B_ * NPC * L_]; // per-chunk MAX of logits
__device__ float  g_cm[B_ * L_];
__device__ float  g_ci[B_ * L_];
__device__ int    g_cnt[B_ * L_];
__device__ int    g_listp[(size_t)B_ * L_ * CAP];
__device__ float  g_listw[(size_t)B_ * L_ * CAP];

// ---------------- helpers ----------------------------------------------------
__device__ __forceinline__ uint32_t smem_u32(const void* p) {
    uint32_t a;
    asm("{ .reg .u64 t; cvta.to.shared.u64 t, %1; cvt.u32.u64 %0, t; }" : "=r"(a) : "l"(p));
    return a;
}
__device__ __forceinline__ void cp_async16(uint32_t saddr, const void* g) {
    asm volatile("cp.async.cg.shared.global [%0], [%1], 16;" :: "r"(saddr), "l"(g));
}
__device__ __forceinline__ void cp_async16z(uint32_t saddr, const void* g, int sz) {
    asm volatile("cp.async.cg.shared.global [%0], [%1], 16, %2;"
                 :: "r"(saddr), "l"(g), "r"(sz));
}
#define CP_COMMIT() asm volatile("cp.async.commit_group;" ::: "memory")
#define CP_WAIT(n)  asm volatile("cp.async.wait_group %0;" :: "n"(n) : "memory")

__device__ __forceinline__ void ldsm_x4(uint32_t& r0, uint32_t& r1, uint32_t& r2,
                                        uint32_t& r3, uint32_t addr) {
    asm volatile("ldmatrix.sync.aligned.m8n8.x4.shared.b16 {%0,%1,%2,%3}, [%4];"
                 : "=r"(r0), "=r"(r1), "=r"(r2), "=r"(r3) : "r"(addr));
}
__device__ __forceinline__ void mma_f16(float c[4], uint32_t a0, uint32_t a1,
                                        uint32_t a2, uint32_t a3,
                                        uint32_t b0, uint32_t b1) {
    asm volatile(
        "mma.sync.aligned.m16n8k16.row.col.f32.f16.f16.f32 "
        "{%0,%1,%2,%3}, {%4,%5,%6,%7}, {%8,%9}, {%0,%1,%2,%3};"
        : "+f"(c[0]), "+f"(c[1]), "+f"(c[2]), "+f"(c[3])
        : "r"(a0), "r"(a1), "r"(a2), "r"(a3), "r"(b0), "r"(b1));
}

// ---------------- k_xd: coalesced downsample + per-pixel S2 ------------------
__global__ __launch_bounds__(256) void k_xd(const float* __restrict__ x) {
    int qy = blockIdx.x, b = blockIdx.y;
    __shared__ __half tile[64 * 130];
    __shared__ float s2p[4][64];
    int tid = threadIdx.x;
    int qx = tid & 63;
    int cg = tid >> 6;
    const float* xrow = x + (size_t)b * C_ * H_ * W_ + (size_t)(2 * qy) * W_;

    float s2 = 0.f;
#pragma unroll 8
    for (int it = 0; it < 32; it++) {
        int c = it * 4 + cg;
        float v = __ldg(&xrow[(size_t)c * (H_ * W_) + 2 * qx]);
        s2 += v * v;
        tile[qx * 130 + c] = __float2half_rn(v);
    }
    s2p[cg][qx] = s2;
    __syncthreads();
    if (tid < 64)
        g_S2[b * L_ + qy * 64 + tid] =
            s2p[0][tid] + s2p[1][tid] + s2p[2][tid] + s2p[3][tid];

    const uint32_t* t32 = (const uint32_t*)tile;
    uint32_t* dst = (uint32_t*)(g_xd + ((size_t)(b * L_ + qy * 64)) * 128);
#pragma unroll
    for (int i = tid; i < 2048; i += 256) {
        int row = i >> 5, w = i & 31;
        dst[row * 64 + w] = t32[row * 65 + w];
    }
}

// ---------------- k_rs: 3x3 stencil on S2 + mask -> rscale/mfilt -------------
__global__ __launch_bounds__(256) void k_rs(const float* __restrict__ mask) {
    int i = blockIdx.x * 256 + threadIdx.x;
    int b = i >> 12, q = i & (L_ - 1);
    int qy = q >> 6, qx = q & 63;
    const float* mb = mask + (size_t)b * (H_ * W_);
    float ss = 0.f, msum = 0.f;
#pragma unroll
    for (int dy = 0; dy < 3; dy++) {
        int sy = qy - 1 + dy;
        if ((unsigned)sy >= HR) continue;
#pragma unroll
        for (int dx = 0; dx < 3; dx++) {
            int sx = qx - 1 + dx;
            if ((unsigned)sx >= HR) continue;
            ss   += __ldg(&g_S2[b * L_ + (sy << 6) + sx]);
            msum += __ldg(&mb[(2 * sy) * W_ + 2 * sx]);
        }
    }
    float denom = sqrtf(ss + F_FULL * EPS_);
    float mf = (msum == 0.f) ? 1.f : 0.f;
    g_mfilt[b * L_ + q]  = mf;
    g_rscale[b * L_ + q] = SCALE_ * mf / denom;
}

// ---------------- k_R: R[p][q] = xd[p] . xd[q]  (K=128, half out) ------------
#define BM 128
#define BN 128
#define BKH 32
#define LDH 40
#define STAGES 3
#define STG_A (BM * LDH * 2)
#define SMEM_R (2 * STAGES * STG_A)

__global__ __launch_bounds__(256) void k_R() {
    int b = blockIdx.z;
    int m0 = blockIdx.y * BM;
    int n0 = blockIdx.x * BN;
    const __half* A = g_xd + (size_t)b * L_ * 128;
    const int lda = 128;
    const int NI = 4;

    extern __shared__ char smem[];
    uint32_t sA = smem_u32(smem);
    uint32_t sB = sA + STAGES * STG_A;

    int tid  = threadIdx.x;
    int wid  = tid >> 5, lane = tid & 31;
    int wm   = wid >> 2, wn = wid & 3;
    int g    = lane >> 2, tig = lane & 3;

    int arow  = lane & 15;
    int acol8 = (lane >> 4) * 8;
    int bmi   = lane >> 3;
    int brow  = (bmi >> 1) * 8 + (lane & 7);
    int bk8   = (bmi & 1) * 8;

    int rowL = tid >> 2, seg = tid & 3;

    float acc[4][4][4];
#pragma unroll
    for (int mt = 0; mt < 4; mt++)
#pragma unroll
        for (int nt = 0; nt < 4; nt++)
#pragma unroll
            for (int k = 0; k < 4; k++) acc[mt][nt][k] = 0.f;

#define ISSUE(it2) do {                                                          \
    int st_ = (it2) % STAGES;                                                    \
    int k0_ = (it2) * BKH;                                                       \
    _Pragma("unroll")                                                            \
    for (int h_ = 0; h_ < 2; h_++) {                                             \
        int row_ = rowL + h_ * 64;                                               \
        cp_async16(sA + st_ * STG_A + (row_ * LDH + seg * 8) * 2,                \
                   &A[(size_t)(m0 + row_) * lda + k0_ + seg * 8]);               \
        cp_async16(sB + st_ * STG_A + (row_ * LDH + seg * 8) * 2,                \
                   &A[(size_t)(n0 + row_) * lda + k0_ + seg * 8]);               \
    }                                                                            \
} while (0)

    ISSUE(0); CP_COMMIT();
    ISSUE(1); CP_COMMIT();

    for (int it = 0; it < NI; it++) {
        CP_WAIT(1);
        __syncthreads();
        if (it + 2 < NI) ISSUE(it + 2);
        CP_COMMIT();

        uint32_t sAb = sA + (it % STAGES) * STG_A;
        uint32_t sBb = sB + (it % STAGES) * STG_A;
#pragma unroll
        for (int ks = 0; ks < 2; ks++) {
            int ko = ks * 16;
            uint32_t af[4][4];
#pragma unroll
            for (int mt = 0; mt < 4; mt++)
                ldsm_x4(af[mt][0], af[mt][1], af[mt][2], af[mt][3],
                        sAb + ((wm * 64 + mt * 16 + arow) * LDH + ko + acol8) * 2);
            uint32_t bf[2][4];
#pragma unroll
            for (int nt2 = 0; nt2 < 2; nt2++)
                ldsm_x4(bf[nt2][0], bf[nt2][1], bf[nt2][2], bf[nt2][3],
                        sBb + ((wn * 32 + nt2 * 16 + brow) * LDH + ko + bk8) * 2);
#pragma unroll
            for (int mt = 0; mt < 4; mt++)
#pragma unroll
                for (int nt = 0; nt < 4; nt++) {
                    int nt2 = nt >> 1, sel = (nt & 1) * 2;
                    mma_f16(acc[mt][nt], af[mt][0], af[mt][1], af[mt][2], af[mt][3],
                            bf[nt2][sel], bf[nt2][sel + 1]);
                }
        }
    }
#undef ISSUE

    __half* Rr = g_R + (size_t)b * L_ * L_;
#pragma unroll
    for (int mt = 0; mt < 4; mt++) {
        int row = m0 + wm * 64 + mt * 16 + g;
#pragma unroll
        for (int nt = 0; nt < 4; nt++) {
            int col = n0 + wn * 32 + nt * 8 + tig * 2;
            *(__half2*)&Rr[(size_t)row * L_ + col] =
                __floats2half2_rn(acc[mt][nt][0], acc[mt][nt][1]);
            *(__half2*)&Rr[(size_t)(row + 8) * L_ + col] =
                __floats2half2_rn(acc[mt][nt][2], acc[mt][nt][3]);
        }
    }
}

// ---------------- k_diag: diagonal logit (lower bound on row max) ------------
__global__ __launch_bounds__(256) void k_diag() {
    int i = blockIdx.x * 256 + threadIdx.x;
    int b = i >> 12, r = i & (L_ - 1);
    int ry = r >> 6, rx = r & 63;
    const __half* Rg = g_R + (size_t)b * L_ * L_;
    float s = 0.f;
#pragma unroll
    for (int dy = -1; dy <= 1; dy++) {
        if ((unsigned)(ry + dy) >= 64u) continue;
#pragma unroll
        for (int dx = -1; dx <= 1; dx++) {
            if ((unsigned)(rx + dx) >= 64u) continue;
            int a = r + 64 * dy + dx;
            s += __half2float(Rg[(size_t)a * L_ + a]);
        }
    }
    g_diag[b * L_ + r] = g_rscale[b * L_ + r] * s;
}

// ---------------- k_att: 4 row-groups per block (2x less L2 traffic) ---------
#define AT_C 512
#define AT_BROWS 18
#define AT_SCOLS 656
#define AT_SC32 (AT_SCOLS / 2)
#define AT_BANDSZ (AT_BROWS * AT_SCOLS * 2)            // 23616
#define AT_SMEM (2 * AT_BANDSZ + AT_C * 4)             // 49280

__global__ __launch_bounds__(256, 2) void k_att() {
    int b   = blockIdx.z;
    int c0  = blockIdx.x * AT_C;
    int qy0 = (blockIdx.y >> 2) << 2;     // 16 values: 0,4,...,60
    int rx0 = (blockIdx.y & 3) << 4;      // 0,16,32,48
    extern __shared__ char smc[];
    float* s_rs = (float*)(smc + 2 * AT_BANDSZ);
    const __half* Rg = g_R + (size_t)b * L_ * L_;
    int tid = threadIdx.x;
    int w = tid >> 5, lane = tid & 31;
    int lane8 = lane & 7;
    uint32_t sbase = smem_u32(smc);

    for (int i = tid; i < AT_C; i += 256) s_rs[i] = g_rscale[b * L_ + c0 + i];

#define ISSUE_BAND(betav, bufv) do {                                             \
    uint32_t bb_ = sbase + (bufv) * AT_BANDSZ;                                   \
    int srow0_ = (qy0 + (betav) - 1) * 64 + rx0 - 1;                             \
    for (int i_ = tid; i_ < AT_BROWS * (AT_SCOLS / 8); i_ += 256) {              \
        int row_ = i_ / (AT_SCOLS / 8);                                          \
        int v8_  = i_ % (AT_SCOLS / 8);                                          \
        int rr_  = srow0_ + row_;                                                \
        int gc0_ = c0 - 72 + v8_ * 8;                                            \
        bool ok_ = ((unsigned)rr_ < (unsigned)L_) && ((unsigned)gc0_ < (unsigned)L_); \
        const void* src_ = ok_ ? (const void*)&Rg[(size_t)rr_ * L_ + gc0_]       \
                               : (const void*)Rg;                                \
        cp_async16z(bb_ + (row_ * AT_SCOLS + v8_ * 8) * 2, src_, ok_ ? 16 : 0);  \
    }                                                                            \
} while (0)

    // acc[group][rr2][pass][word]
    uint32_t acc[4][2][2][4];
#pragma unroll
    for (int g = 0; g < 4; g++)
#pragma unroll
        for (int a = 0; a < 2; a++)
#pragma unroll
            for (int p = 0; p < 2; p++)
#pragma unroll
                for (int k = 0; k < 4; k++) acc[g][a][p][k] = 0u;

    ISSUE_BAND(0, 0);
    CP_COMMIT();

    for (int beta = 0; beta < 6; beta++) {
        if (beta > 0) __syncthreads();
        if (beta < 5) ISSUE_BAND(beta + 1, (beta + 1) & 1);
        CP_COMMIT();
        if (beta < 5) { CP_WAIT(1); } else { CP_WAIT(0); }
        __syncthreads();
        if ((unsigned)(qy0 + beta - 1) >= 64u) continue;   // band fully out of range

        const uint32_t* sB32 = (const uint32_t*)(smc + (beta & 1) * AT_BANDSZ);
#pragma unroll
        for (int g = 0; g < 4; g++) {
            int dy = beta - g - 1;
            if (dy < -1 || dy > 1) continue;
#pragma unroll
            for (int rr2 = 0; rr2 < 2; rr2++) {
                int k = w * 2 + rr2;
                int rx = rx0 + k;
                uint32_t aAll = (rx > 0)  ? 0xFFFFFFFFu : 0u;
                uint32_t cAll = (rx < 63) ? 0xFFFFFFFFu : 0u;
                uint32_t mA0 = ((lane8 == 0) ? 0xFFFF0000u : 0xFFFFFFFFu) & aAll;
                uint32_t mC3 = ((lane8 == 7) ? 0x0000FFFFu : 0xFFFFFFFFu) & cAll;
#pragma unroll
                for (int pass = 0; pass < 2; pass++) {
                    int lc = pass * 256 + lane * 8;
                    int cy = (c0 + lc) >> 6;
                    if ((unsigned)(cy + dy) >= 64u) continue;
                    int wb = (lc + 64 * dy + 72) >> 1;
                    const uint32_t* r0p = sB32 + k * AT_SC32;
                    const uint32_t* r1p = sB32 + (k + 1) * AT_SC32;
                    const uint32_t* r2p = sB32 + (k + 2) * AT_SC32;
                    uint32_t aw = r0p[wb - 1];
                    uint4 av = *(const uint4*)(r0p + wb);
                    uint4 bv = *(const uint4*)(r1p + wb);
                    uint4 cv = *(const uint4*)(r2p + wb);
                    uint32_t cw = r2p[wb + 4];

                    uint32_t A2[4], C2[4];
                    A2[0] = __byte_perm(aw,   av.x, 0x5432) & mA0;
                    A2[1] = __byte_perm(av.x, av.y, 0x5432) & aAll;
                    A2[2] = __byte_perm(av.y, av.z, 0x5432) & aAll;
                    A2[3] = __byte_perm(av.z, av.w, 0x5432) & aAll;
                    C2[0] = __byte_perm(cv.x, cv.y, 0x5432) & cAll;
                    C2[1] = __byte_perm(cv.y, cv.z, 0x5432) & cAll;
                    C2[2] = __byte_perm(cv.z, cv.w, 0x5432) & cAll;
                    C2[3] = __byte_perm(cv.w, cw,   0x5432) & mC3;
                    const uint32_t* bw = (const uint32_t*)&bv;
#pragma unroll
                    for (int kk = 0; kk < 4; kk++) {
                        __half2 t = __hadd2(*(__half2*)&A2[kk], *(__half2*)&bw[kk]);
                        t = __hadd2(t, *(__half2*)&C2[kk]);
                        *(__half2*)&acc[g][rr2][pass][kk] =
                            __hadd2(*(__half2*)&acc[g][rr2][pass][kk], t);
                    }
                }
            }
        }
    }
#undef ISSUE_BAND

    // epilogue: scale by rs, chunk max, GATED store (R14 gate: diag - 20)
    __half* att = g_att + (size_t)b * L_ * L_;
#pragma unroll
    for (int g = 0; g < 4; g++) {
#pragma unroll
        for (int rr2 = 0; rr2 < 2; rr2++) {
            int r = (qy0 + g) * 64 + rx0 + w * 2 + rr2;
            float dgate = g_diag[b * L_ + r] - 20.f;
#pragma unroll
            for (int pass = 0; pass < 2; pass++) {
                int lc = pass * 256 + lane * 8;
                float4 rs0 = *(float4*)&s_rs[lc];
                float4 rs1 = *(float4*)&s_rs[lc + 4];
                float rsv[8] = {rs0.x, rs0.y, rs0.z, rs0.w, rs1.x, rs1.y, rs1.z, rs1.w};
                uint32_t outw[4];
                __half2 mx2 = __float2half2_rn(-60000.f);
#pragma unroll
                for (int kk = 0; kk < 4; kk++) {
                    float2 f = __half22float2(*(__half2*)&acc[g][rr2][pass][kk]);
                    __half2 h = __floats2half2_rn(f.x * rsv[2 * kk], f.y * rsv[2 * kk + 1]);
                    outw[kk] = *(uint32_t*)&h;
                    mx2 = __hmax2(mx2, h);
                }
                float m = fmaxf(__low2float(mx2), __high2float(mx2));
#pragma unroll
                for (int off = 8; off > 0; off >>= 1)
                    m = fmaxf(m, __shfl_xor_sync(0xffffffffu, m, off));
                if (m >= dgate)
                    *(uint4*)&att[(size_t)r * L_ + c0 + lc] = *(uint4*)outw;
                if ((lane & 15) == 0) {
                    int pc = (c0 + lc) >> 7;
                    g_statm[((size_t)b * NPC + pc) * L_ + r] = m;
                }
            }
        }
    }
}

// ---------------- k_smC: M from chunk maxima, gated S, gated list ------------
__global__ __launch_bounds__(256) void k_smC() {
    int b = blockIdx.y;
    int wid = threadIdx.x >> 5, lane = threadIdx.x & 31;
    int r = blockIdx.x * 8 + wid;
    const __half* Ar = g_att + (size_t)b * L_ * L_ + (size_t)r * L_;
    const float* mfp = g_mfilt + b * L_;

    float cm = g_statm[((size_t)b * NPC + lane) * L_ + r];
    float M = cm;
#pragma unroll
    for (int off = 16; off > 0; off >>= 1)
        M = fmaxf(M, __shfl_xor_sync(0xffffffffu, M, off));

    unsigned qmask = __ballot_sync(0xffffffffu, cm >= M - 20.f);

    float S = 0.f;
    unsigned qm = qmask;
    while (qm) {
        int pc = __ffs(qm) - 1;
        qm &= qm - 1;
        int c = pc * 128 + lane * 4;
        uint2 v = *(const uint2*)&Ar[c];
        __half2 h0 = *(__half2*)&v.x, h1 = *(__half2*)&v.y;
        float s4 = __expf(__low2float(h0) - M) + __expf(__high2float(h0) - M)
                 + __expf(__low2float(h1) - M) + __expf(__high2float(h1) - M);
#pragma unroll
        for (int off = 16; off > 0; off >>= 1)
            s4 += __shfl_xor_sync(0xffffffffu, s4, off);
        S += s4;
    }
    float Iv = 1.f / S;
    if (lane == 0) { g_cm[b * L_ + r] = M; g_ci[b * L_ + r] = Iv; }

    int cnt = 0;
    size_t base = (size_t)(b * L_ + r) * CAP;
    while (qmask) {
        int pc = __ffs(qmask) - 1;
        qmask &= qmask - 1;
        int c = pc * 128 + lane * 4;
        uint2 v = *(const uint2*)&Ar[c];
        __half2 h0 = *(__half2*)&v.x, h1 = *(__half2*)&v.y;
        float4 mfv = *(const float4*)&mfp[c];
        float wv[4];
        wv[0] = __expf(__low2float(h0) - M) * Iv * mfv.x;
        wv[1] = __expf(__high2float(h0) - M) * Iv * mfv.y;
        wv[2] = __expf(__low2float(h1) - M) * Iv * mfv.z;
        wv[3] = __expf(__high2float(h1) - M) * Iv * mfv.w;
        int lcount = (wv[0] >= THRESH) + (wv[1] >= THRESH) + (wv[2] >= THRESH) + (wv[3] >= THRESH);
        int incl = lcount;
#pragma unroll
        for (int d = 1; d < 32; d <<= 1) {
            int o2 = __shfl_up_sync(0xffffffffu, incl, d);
            if (lane >= d) incl += o2;
        }
        int idx = cnt + incl - lcount;
#pragma unroll
        for (int k = 0; k < 4; k++)
            if (wv[k] >= THRESH) {
                if (idx < CAP) { g_listp[base + idx] = c + k; g_listw[base + idx] = wv[k]; }
                idx++;
            }
        cnt += __shfl_sync(0xffffffffu, incl, 31);
    }
    if (lane == 0) g_cnt[b * L_ + r] = cnt;
}

// ---------------- fused sparse apply + overlap-add (channel-amortized) -------
__global__ __launch_bounds__(128) void k_out(const float* __restrict__ x,
                                             float* __restrict__ out) {
    int y = blockIdx.x, cg = blockIdx.y, b = blockIdx.z;
    int xx = threadIdx.x;
    int c0 = cg * 16;
    const float* xb = x + (size_t)(b * C_ + c0) * (H_ * W_);
    float acc[16];
#pragma unroll
    for (int k = 0; k < 16; k++) acc[k] = 0.f;

    int ki0 = (y + 1) & 1, kj0 = (xx + 1) & 1;
#pragma unroll
    for (int a = 0; a < 2; a++) {
        int ki = ki0 + a * 2;
        int sy2 = y + 1 - ki;
        if (sy2 < 0) continue;
        int sy = sy2 >> 1;
        if (sy >= HR) continue;
#pragma unroll
        for (int bb = 0; bb < 2; bb++) {
            int kj = kj0 + bb * 2;
            int sx2 = xx + 1 - kj;
            if (sx2 < 0) continue;
            int sx = sx2 >> 1;
            if (sx >= HR) continue;
            int q = (sy << 6) + sx;
            int cnt = g_cnt[b * L_ + q];
            if (cnt <= CAP) {
                size_t base = (size_t)(b * L_ + q) * CAP;
                for (int t = 0; t < cnt; t++) {
                    int p = g_listp[base + t];
                    float wv = g_listw[base + t];
                    int py = p >> 6, px = p & 63;
                    int ry = 2 * py - 1 + ki, rx = 2 * px - 1 + kj;
                    if ((unsigned)ry < H_ && (unsigned)rx < W_) {
                        int off = ry * W_ + rx;
#pragma unroll
                        for (int cn = 0; cn < 16; cn++)
                            acc[cn] += wv * __ldg(&xb[(size_t)cn * (H_ * W_) + off]);
                    }
                }
            } else {
                // dense fallback over GATED (stored) chunks only
                const __half* Ar = g_att + (size_t)b * L_ * L_ + (size_t)q * L_;
                float M = g_cm[b * L_ + q], Iv = g_ci[b * L_ + q];
                const float* mfp = g_mfilt + b * L_;
                for (int pc = 0; pc < NPC; pc++) {
                    if (g_statm[((size_t)b * NPC + pc) * L_ + q] < M - 20.f) continue;
                    for (int pl = 0; pl < 128; pl++) {
                        int p = pc * 128 + pl;
                        float wv = __expf(__half2float(Ar[p]) - M) * Iv * mfp[p];
                        if (wv < THRESH) continue;
                        int py = p >> 6, px = p & 63;
                        int ry = 2 * py - 1 + ki, rx = 2 * px - 1 + kj;
                        if ((unsigned)ry < H_ && (unsigned)rx < W_) {
                            int off = ry * W_ + rx;
                            for (int cn = 0; cn < 16; cn++)
                                acc[cn] += wv * __ldg(&xb[(size_t)cn * (H_ * W_) + off]);
                        }
                    }
                }
            }
        }
    }
#pragma unroll
    for (int cn = 0; cn < 16; cn++)
        out[(((size_t)(b * C_ + c0 + cn)) * H_ + y) * W_ + xx] = 0.25f * acc[cn];
}

// ---------------- launch ------------------------------------------------------
extern "C" void kernel_launch(void* const* d_in, const int* in_sizes, int n_in,
                              void* d_out, int out_size) {
    const float* x    = (const float*)d_in[0];
    const float* mask = (const float*)d_in[1];
    float* out = (float*)d_out;

    cudaFuncSetAttribute(k_R, cudaFuncAttributeMaxDynamicSharedMemorySize, SMEM_R);
    cudaFuncSetAttribute(k_att, cudaFuncAttributeMaxDynamicSharedMemorySize, AT_SMEM);

    k_xd<<<dim3(HR, B_), 256>>>(x);
    k_rs<<<(B_ * L_) / 256, 256>>>(mask);
    k_R<<<dim3(L_ / BN, L_ / BM, B_), 256, SMEM_R>>>();
    k_diag<<<(B_ * L_) / 256, 256>>>();
    k_att<<<dim3(L_ / AT_C, 64, B_), 256, AT_SMEM>>>();
    k_smC<<<dim3(L_ / 8, B_), 256>>>();
    k_out<<<dim3(H_, 8, B_), 128>>>(x, out);
}